// round 11
// baseline (speedup 1.0000x reference)
#include <cuda_runtime.h>
#include <cuda_bf16.h>
#include <math.h>
#include <stdint.h>

// Problem constants (from reference setup_inputs)
#define NTOK   16384      // B*D = 4*4096
#define CDIM   320
#define PCACHE 32
#define RSEL   8
#define HEADS_ 8
#define DH     40
#define NKEY   9          // RSEL + 1

// ---------------- device scratch (static, no allocs) ----------------
__device__ float  d_W3[CDIM * 3 * CDIM];                 // [Wq | Wk | Wv] (320 x 960)
__device__ float  d_P [NTOK * 3 * CDIM];                 // [q_now | k_now | v_now] (16384 x 960)
__device__ float  d_kpast[(size_t)NTOK * PCACHE * CDIM]; // full k_past (524288 x 320)
__device__ int    d_rowmap[NTOK * RSEL];                 // absolute cached-row index (t*32 + sel)
__device__ float  d_vsel[NTOK * RSEL * CDIM];            // selected v_past rows (131072 x 320)
__device__ float  d_ctx [NTOK * CDIM];                   // context before Wo
__device__ float2 d_rope[NKEY * (CDIM/2)];               // cos/sin per (pos, freq)

// ---------------- rope tables, fp32 libdevice semantics matching XLA ----------------
__global__ void rope_table_kernel()
{
    int idx = blockIdx.x * blockDim.x + threadIdx.x;
    if (idx >= NKEY * (CDIM/2)) return;
    int pos = idx / (CDIM/2);
    int ip  = idx - pos * (CDIM/2);
    float x   = __fdiv_rn((float)(2 * ip), (float)CDIM);
    float pw  = powf(10000.0f, x);
    float inv = __fdiv_rn(1.0f, pw);
    float ang = __fmul_rn((float)pos, inv);
    d_rope[idx] = make_float2(cosf(ang), sinf(ang));
}

// ---------------- prep: W3 = [Wq | Wk | Wv] (320 x 960) ----------------
__global__ void pack_W3_kernel(const float* __restrict__ Wq, const float* __restrict__ Wk,
                               const float* __restrict__ Wv)
{
    int idx = blockIdx.x * 256 + threadIdx.x;
    if (idx >= CDIM * 3 * CDIM) return;
    int a = idx / (3 * CDIM), j = idx - a * (3 * CDIM);
    float v;
    if (j < CDIM)            v = Wq[a * CDIM + j];
    else if (j < 2 * CDIM)   v = Wk[a * CDIM + j - CDIM];
    else                     v = Wv[a * CDIM + j - 2 * CDIM];
    d_W3[idx] = v;
}

// ---------------- packed-f32x2 helpers ----------------
// Each 32-bit lane of fma.rn.f32x2 rounds RN exactly like scalar __fmaf_rn: pairing two
// OUTPUT COLUMNS per 64-bit accumulator keeps every per-element chain bit-identical
// (single fp32 accumulator per output, FMA, k strictly ascending).
__device__ __forceinline__ uint64_t dup2(float v)
{
    uint64_t r;
    asm("mov.b64 %0, {%1, %1};" : "=l"(r) : "f"(v));
    return r;
}
__device__ __forceinline__ void ffma2(uint64_t& acc, uint64_t a, uint64_t b)
{
    asm("fma.rn.f32x2 %0, %1, %2, %0;" : "+l"(acc) : "l"(a), "l"(b));
}
__device__ __forceinline__ void unpack2(uint64_t v, float& lo, float& hi)
{
    asm("mov.b64 {%0, %1}, %2;" : "=f"(lo), "=f"(hi) : "l"(v));
}

// ---------------- fast fp32 GEMM (FFMA2): C = A(MxK) @ B(KxN) (+bias) ---------------
// BM=256, BN=64, BK=16, 256 threads, 8x8 per thread, double-buffered smem.
// GRID LAYOUT: blockIdx.x = N-block, blockIdx.y = M-block — consecutive bids share the
// same A tile (read once from DRAM, served to siblings from L2).
// Requirements: M % 256 == 0, N % 64 == 0, K % 16 == 0.
template <bool GATHER, bool BIAS>
__global__ void __launch_bounds__(256, 2)
gemm_fast(const float* __restrict__ A, const float* __restrict__ B, float* __restrict__ C,
          int Kdim, int lda, int ldb, int ldc,
          const int* __restrict__ rowmap, const float* __restrict__ bias)
{
    const int BM = 256, BN = 64, BK = 16;
    __shared__ float As[2][BK][BM];   // 2 x 16 KB
    __shared__ float Bs[2][BK][BN];   // 2 x 4 KB

    int tid  = threadIdx.x;
    int row0 = blockIdx.y * BM;
    int col0 = blockIdx.x * BN;

    // A loads: one row per thread, 16 consecutive k as 4x float4
    int grow = row0 + tid;
    if (GATHER) grow = rowmap[grow];
    const float* ap = A + (size_t)grow * lda;

    // B loads: one float4 per thread: k-row bkr, cols bcl..bcl+3
    int bkr = tid >> 4;              // 0..15
    int bcl = (tid & 15) * 4;        // 0..60
    const float* bp = B + (size_t)bkr * ldb + col0 + bcl;

    int tx = tid & 7, ty = tid >> 3; // tx: col octet 0..7, ty: row octet 0..31
    uint64_t acc2[8][4];             // [row i][col pair jp] — lanes = cols tx*8+2jp, +1
#pragma unroll
    for (int i = 0; i < 8; i++)
#pragma unroll
        for (int jp = 0; jp < 4; jp++) acc2[i][jp] = 0ull;

    int NT = Kdim / BK;

    // prefetch tile 0
    float4 ar[4];
    float4 br;
#pragma unroll
    for (int q = 0; q < 4; q++) ar[q] = *reinterpret_cast<const float4*>(ap + q * 4);
    br = *reinterpret_cast<const float4*>(bp);
#pragma unroll
    for (int q = 0; q < 4; q++) {
        As[0][q * 4 + 0][tid] = ar[q].x; As[0][q * 4 + 1][tid] = ar[q].y;
        As[0][q * 4 + 2][tid] = ar[q].z; As[0][q * 4 + 3][tid] = ar[q].w;
    }
    *reinterpret_cast<float4*>(&Bs[0][bkr][bcl]) = br;
    __syncthreads();

    int buf = 0;
    for (int t = 0; t < NT; t++) {
        if (t + 1 < NT) {
#pragma unroll
            for (int q = 0; q < 4; q++)
                ar[q] = *reinterpret_cast<const float4*>(ap + (t + 1) * BK + q * 4);
            br = *reinterpret_cast<const float4*>(bp + (size_t)(t + 1) * BK * ldb);
        }
#pragma unroll
        for (int kk = 0; kk < BK; kk++) {   // ascending k: k = t*16 + kk
            float4 av0 = *reinterpret_cast<const float4*>(&As[buf][kk][ty * 8]);
            float4 av1 = *reinterpret_cast<const float4*>(&As[buf][kk][ty * 8 + 4]);
            // B column pairs read directly as 64-bit (no pack MOVs)
            const uint64_t* b64 = reinterpret_cast<const uint64_t*>(&Bs[buf][kk][tx * 8]);
            uint64_t bpair[4] = {b64[0], b64[1], b64[2], b64[3]};
            float av[8] = {av0.x, av0.y, av0.z, av0.w, av1.x, av1.y, av1.z, av1.w};
#pragma unroll
            for (int i = 0; i < 8; i++) {
                uint64_t ad = dup2(av[i]);
#pragma unroll
                for (int jp = 0; jp < 4; jp++)
                    ffma2(acc2[i][jp], ad, bpair[jp]);
            }
        }
        if (t + 1 < NT) {
            int nb = buf ^ 1;
#pragma unroll
            for (int q = 0; q < 4; q++) {
                As[nb][q * 4 + 0][tid] = ar[q].x; As[nb][q * 4 + 1][tid] = ar[q].y;
                As[nb][q * 4 + 2][tid] = ar[q].z; As[nb][q * 4 + 3][tid] = ar[q].w;
            }
            *reinterpret_cast<float4*>(&Bs[nb][bkr][bcl]) = br;
            __syncthreads();
            buf = nb;
        }
    }

    int gc = col0 + tx * 8;
#pragma unroll
    for (int i = 0; i < 8; i++) {
        int r = row0 + ty * 8 + i;
        float o[8];
        unpack2(acc2[i][0], o[0], o[1]);
        unpack2(acc2[i][1], o[2], o[3]);
        unpack2(acc2[i][2], o[4], o[5]);
        unpack2(acc2[i][3], o[6], o[7]);
        if (BIAS) {
#pragma unroll
            for (int j = 0; j < 8; j++) o[j] = __fadd_rn(o[j], bias[gc + j]);
        }
        *reinterpret_cast<float4*>(C + (size_t)r * ldc + gc)     = make_float4(o[0], o[1], o[2], o[3]);
        *reinterpret_cast<float4*>(C + (size_t)r * ldc + gc + 4) = make_float4(o[4], o[5], o[6], o[7]);
    }
}

// ---------------- scores: warp-per-dot, lane-strided (stride 32) + shfl tree --------
// FROZEN — bit-matches the reference's score lowering (selection-critical).
__global__ void __launch_bounds__(256)
scores_topk_kernel(int* __restrict__ rowmap)
{
    int t = blockIdx.x;
    __shared__ float qs[CDIM];
    __shared__ float sc[PCACHE];
    int tid = threadIdx.x;
    for (int i = tid; i < CDIM; i += 256) qs[i] = d_P[(size_t)t * 960 + i];
    __syncthreads();

    int w = tid >> 5, lane = tid & 31;
#pragma unroll
    for (int r = 0; r < 4; r++) {
        int p = w * 4 + r;
        const float* krow = d_kpast + ((size_t)t * PCACHE + p) * CDIM;
        float acc = 0.f;
#pragma unroll
        for (int i = 0; i < CDIM / 32; i++)
            acc = __fmaf_rn(qs[lane + 32 * i], krow[lane + 32 * i], acc);
#pragma unroll
        for (int off = 16; off; off >>= 1)
            acc = __fadd_rn(acc, __shfl_down_sync(0xffffffffu, acc, off));
        if (lane == 0) sc[p] = acc;
    }
    __syncthreads();

    if (tid == 0) {
        unsigned used = 0;
#pragma unroll
        for (int j = 0; j < RSEL; j++) {
            float best = -3.402823466e38f; int bi = 0;
            for (int p = 0; p < PCACHE; p++) {
                if (!((used >> p) & 1u) && sc[p] > best) { best = sc[p]; bi = p; }
            }
            used |= (1u << bi);
            rowmap[t * RSEL + j] = t * PCACHE + bi;
        }
    }
}

// ---------------- attention: RoPE (mul/sub, no FMA), serial softmax, serial FMA ------
__global__ void __launch_bounds__(256)
attn_kernel(const int* __restrict__ rowmap)
{
    int t = blockIdx.x, tid = threadIdx.x;
    __shared__ float q[CDIM];
    __shared__ float kb[NKEY][CDIM];
    __shared__ float vb[NKEY][CDIM];
    __shared__ float sw[HEADS_][NKEY];
    __shared__ int rows[RSEL];

    if (tid < RSEL) rows[tid] = rowmap[t * RSEL + tid];
    for (int i = tid; i < CDIM; i += 256) q[i] = d_P[(size_t)t * 960 + i];
    __syncthreads();

    for (int i = tid; i < NKEY * CDIM; i += 256) {
        int j = i / CDIM, c = i - j * CDIM;
        kb[j][c] = (j < RSEL) ? d_kpast[(size_t)rows[j] * CDIM + c]
                              : d_P[(size_t)t * 960 + CDIM + c];       // k_now
        vb[j][c] = (j < RSEL) ? d_vsel[(size_t)(t * RSEL + j) * CDIM + c]
                              : d_P[(size_t)t * 960 + 2 * CDIM + c];   // v_now
    }
    __syncthreads();

    for (int pidx = tid; pidx < NKEY * (CDIM/2); pidx += 256) {
        int j = pidx / (CDIM/2), ip = pidx - j * (CDIM/2);
        float2 cs = d_rope[j * (CDIM/2) + ip];
        float e = kb[j][2*ip], o = kb[j][2*ip + 1];
        kb[j][2*ip]     = __fsub_rn(__fmul_rn(e, cs.x), __fmul_rn(o, cs.y));
        kb[j][2*ip + 1] = __fadd_rn(__fmul_rn(e, cs.y), __fmul_rn(o, cs.x));
    }
    __syncthreads();

    if (tid < HEADS_ * NKEY) {
        int h = tid / NKEY, j = tid - h * NKEY;
        float s = 0.f;
#pragma unroll
        for (int d = 0; d < DH; d++)
            s = __fmaf_rn(q[h * DH + d], kb[j][h * DH + d], s);
        sw[h][j] = __fmul_rn(s, 0.15811388300841897f);
    }
    __syncthreads();

    if (tid < HEADS_) {
        int h = tid;
        float mx = sw[h][0];
#pragma unroll
        for (int j = 1; j < NKEY; j++) mx = fmaxf(mx, sw[h][j]);
        float e[NKEY]; float sum = 0.f;
#pragma unroll
        for (int j = 0; j < NKEY; j++) {
            e[j] = expf(__fsub_rn(sw[h][j], mx));
            sum = __fadd_rn(sum, e[j]);
        }
#pragma unroll
        for (int j = 0; j < NKEY; j++) sw[h][j] = __fdiv_rn(e[j], sum);
    }
    __syncthreads();

    for (int c = tid; c < CDIM; c += 256) {
        int h = c / DH;
        float acc = 0.f;
#pragma unroll
        for (int j = 0; j < NKEY; j++)
            acc = __fmaf_rn(sw[h][j], vb[j][c], acc);
        d_ctx[(size_t)t * CDIM + c] = acc;
    }
}

// ---------------- launch ----------------
extern "C" void kernel_launch(void* const* d_in, const int* in_sizes, int n_in,
                              void* d_out, int out_size)
{
    const float* hidden = (const float*)d_in[0];
    const float* cached = (const float*)d_in[1];
    const float* Wq     = (const float*)d_in[2];
    const float* Wk     = (const float*)d_in[3];
    const float* Wv     = (const float*)d_in[4];
    const float* Wo     = (const float*)d_in[5];
    const float* bo     = (const float*)d_in[6];
    float* out = (float*)d_out;

    float *pW3, *pP, *pKpast, *pVsel, *pCtx;
    int* pRow;
    cudaGetSymbolAddress((void**)&pW3,    d_W3);
    cudaGetSymbolAddress((void**)&pP,     d_P);
    cudaGetSymbolAddress((void**)&pKpast, d_kpast);
    cudaGetSymbolAddress((void**)&pVsel,  d_vsel);
    cudaGetSymbolAddress((void**)&pCtx,   d_ctx);
    cudaGetSymbolAddress((void**)&pRow,   d_rowmap);

    rope_table_kernel<<<6, 256>>>();
    pack_W3_kernel<<<(CDIM * 3 * CDIM + 255) / 256, 256>>>(Wq, Wk, Wv);

    // [q_now | k_now | v_now] = hidden @ [Wq|Wk|Wv]   (16384 x 960)
    gemm_fast<false, false><<<dim3(960 / 64, NTOK / 256), 256>>>(
        hidden, pW3, pP, CDIM, CDIM, 960, 960, nullptr, nullptr);

    // k_past = cached @ Wk   (524288 x 320) — N-blocks inner for L2 A-sharing
    gemm_fast<false, false><<<dim3(CDIM / 64, NTOK * PCACHE / 256), 256>>>(
        cached, Wk, pKpast, CDIM, CDIM, CDIM, CDIM, nullptr, nullptr);

    // scores (gemv2T-order, FROZEN) + top-8 -> rowmap
    scores_topk_kernel<<<NTOK, 256>>>(pRow);

    // v_sel = cached[rowmap] @ Wv   (131072 x 320)
    gemm_fast<true, false><<<dim3(CDIM / 64, NTOK * RSEL / 256), 256>>>(
        cached, Wv, pVsel, CDIM, CDIM, CDIM, CDIM, pRow, nullptr);

    // RoPE + attention + ctx
    attn_kernel<<<NTOK, 256>>>(pRow);

    // out = ctx @ Wo + bo
    gemm_fast<false, true><<<dim3(CDIM / 64, NTOK / 256), 256>>>(
        pCtx, Wo, out, CDIM, CDIM, CDIM, CDIM, nullptr, bo);
}

// round 12
// speedup vs baseline: 1.0477x; 1.0477x over previous
#include <cuda_runtime.h>
#include <cuda_bf16.h>
#include <math.h>
#include <stdint.h>

// Problem constants (from reference setup_inputs)
#define NTOK   16384      // B*D = 4*4096
#define CDIM   320
#define PCACHE 32
#define RSEL   8
#define HEADS_ 8
#define DH     40
#define NKEY   9          // RSEL + 1

// ---------------- device scratch (static, no allocs) ----------------
__device__ float  d_W3[CDIM * 3 * CDIM];                 // [Wq | Wk | Wv] (320 x 960)
__device__ float  d_P [NTOK * 3 * CDIM];                 // [q_now | k_now | v_now] (16384 x 960)
__device__ float  d_kpast[(size_t)NTOK * PCACHE * CDIM]; // full k_past (524288 x 320)
__device__ int    d_rowmap[NTOK * RSEL];                 // absolute cached-row index (t*32 + sel)
__device__ float  d_vsel[NTOK * RSEL * CDIM];            // selected v_past rows (131072 x 320)
__device__ float  d_ctx [NTOK * CDIM];                   // context before Wo
__device__ float2 d_rope[NKEY * (CDIM/2)];               // cos/sin per (pos, freq)

// ---------------- rope tables, fp32 libdevice semantics matching XLA ----------------
__global__ void rope_table_kernel()
{
    int idx = blockIdx.x * blockDim.x + threadIdx.x;
    if (idx >= NKEY * (CDIM/2)) return;
    int pos = idx / (CDIM/2);
    int ip  = idx - pos * (CDIM/2);
    float x   = __fdiv_rn((float)(2 * ip), (float)CDIM);
    float pw  = powf(10000.0f, x);
    float inv = __fdiv_rn(1.0f, pw);
    float ang = __fmul_rn((float)pos, inv);
    d_rope[idx] = make_float2(cosf(ang), sinf(ang));
}

// ---------------- prep: W3 = [Wq | Wk | Wv] (320 x 960) ----------------
__global__ void pack_W3_kernel(const float* __restrict__ Wq, const float* __restrict__ Wk,
                               const float* __restrict__ Wv)
{
    int idx = blockIdx.x * 256 + threadIdx.x;
    if (idx >= CDIM * 3 * CDIM) return;
    int a = idx / (3 * CDIM), j = idx - a * (3 * CDIM);
    float v;
    if (j < CDIM)            v = Wq[a * CDIM + j];
    else if (j < 2 * CDIM)   v = Wk[a * CDIM + j - CDIM];
    else                     v = Wv[a * CDIM + j - 2 * CDIM];
    d_W3[idx] = v;
}

// ---------------- packed-f32x2 helpers ----------------
// Each 32-bit lane of fma.rn.f32x2 rounds RN exactly like scalar __fmaf_rn: pairing two
// OUTPUT COLUMNS per 64-bit accumulator keeps every per-element chain bit-identical
// (single fp32 accumulator per output, FMA, k strictly ascending).
__device__ __forceinline__ uint64_t dup2(float v)
{
    uint64_t r;
    asm("mov.b64 %0, {%1, %1};" : "=l"(r) : "f"(v));
    return r;
}
__device__ __forceinline__ void ffma2(uint64_t& acc, uint64_t a, uint64_t b)
{
    asm("fma.rn.f32x2 %0, %1, %2, %0;" : "+l"(acc) : "l"(a), "l"(b));
}
__device__ __forceinline__ void unpack2(uint64_t v, float& lo, float& hi)
{
    asm("mov.b64 {%0, %1}, %2;" : "=f"(lo), "=f"(hi) : "l"(v));
}

// ---------------- fast fp32 GEMM (FFMA2, 16x8 tile): C = A @ B (+bias) --------------
// BM=512, BN=64, BK=8, 256 threads, 16 rows x 8 cols per thread, double-buffered smem.
// smem traffic: 96 B per 128 FMA per thread-kk (0.75 B/FMA) — below the crossbar
// balance point, so FFMA2 issue becomes the limiter.
// blockIdx.x = N-block, blockIdx.y = M-block (A tiles shared via L2 across x-siblings).
// Per output element: ONE fp32 accumulator, FMA, k strictly ascending (bit-frozen).
// Requirements: M % 512 == 0, N % 64 == 0, K % 8 == 0.
template <bool GATHER, bool BIAS>
__global__ void __launch_bounds__(256, 1)
gemm_fast(const float* __restrict__ A, const float* __restrict__ B, float* __restrict__ C,
          int Kdim, int lda, int ldb, int ldc,
          const int* __restrict__ rowmap, const float* __restrict__ bias)
{
    const int BM = 512, BN = 64, BK = 8;
    __shared__ float As[2][BK][BM];   // 2 x 16 KB
    __shared__ float Bs[2][BK][BN];   // 2 x 2 KB

    int tid  = threadIdx.x;
    int row0 = blockIdx.y * BM;
    int col0 = blockIdx.x * BN;

    // A loads: 2 rows per thread (tid, tid+256), 8 k each as 2x float4
    int g0 = row0 + tid, g1 = row0 + tid + 256;
    if (GATHER) { g0 = rowmap[g0]; g1 = rowmap[g1]; }
    const float* ap0 = A + (size_t)g0 * lda;
    const float* ap1 = A + (size_t)g1 * lda;

    // B loads: 1 float2 per thread: k-row bkr, cols bcl..bcl+1
    int bkr = tid >> 5;              // 0..7
    int bcl = (tid & 31) * 2;        // 0..62
    const float* bp = B + (size_t)bkr * ldb + col0 + bcl;

    int tx = tid & 7, ty = tid >> 3; // tx: col octet 0..7, ty: row 16-group 0..31
    uint64_t acc2[16][4];            // [row i][col pair jp]
#pragma unroll
    for (int i = 0; i < 16; i++)
#pragma unroll
        for (int jp = 0; jp < 4; jp++) acc2[i][jp] = 0ull;

    int NT = Kdim / BK;              // 40 for K=320

    // prefetch tile 0
    float4 a00 = *reinterpret_cast<const float4*>(ap0);
    float4 a01 = *reinterpret_cast<const float4*>(ap0 + 4);
    float4 a10 = *reinterpret_cast<const float4*>(ap1);
    float4 a11 = *reinterpret_cast<const float4*>(ap1 + 4);
    float2 b0  = *reinterpret_cast<const float2*>(bp);
    As[0][0][tid] = a00.x; As[0][1][tid] = a00.y; As[0][2][tid] = a00.z; As[0][3][tid] = a00.w;
    As[0][4][tid] = a01.x; As[0][5][tid] = a01.y; As[0][6][tid] = a01.z; As[0][7][tid] = a01.w;
    As[0][0][tid + 256] = a10.x; As[0][1][tid + 256] = a10.y;
    As[0][2][tid + 256] = a10.z; As[0][3][tid + 256] = a10.w;
    As[0][4][tid + 256] = a11.x; As[0][5][tid + 256] = a11.y;
    As[0][6][tid + 256] = a11.z; As[0][7][tid + 256] = a11.w;
    Bs[0][bkr][bcl] = b0.x; Bs[0][bkr][bcl + 1] = b0.y;
    __syncthreads();

    int buf = 0;
    for (int t = 0; t < NT; t++) {
        if (t + 1 < NT) {
            a00 = *reinterpret_cast<const float4*>(ap0 + (t + 1) * BK);
            a01 = *reinterpret_cast<const float4*>(ap0 + (t + 1) * BK + 4);
            a10 = *reinterpret_cast<const float4*>(ap1 + (t + 1) * BK);
            a11 = *reinterpret_cast<const float4*>(ap1 + (t + 1) * BK + 4);
            b0  = *reinterpret_cast<const float2*>(bp + (size_t)(t + 1) * BK * ldb);
        }
#pragma unroll
        for (int kk = 0; kk < BK; kk++) {   // ascending k: k = t*8 + kk
            // A: 16 consecutive rows for this thread (4x LDS.128)
            float4 av0 = *reinterpret_cast<const float4*>(&As[buf][kk][ty * 16]);
            float4 av1 = *reinterpret_cast<const float4*>(&As[buf][kk][ty * 16 + 4]);
            float4 av2 = *reinterpret_cast<const float4*>(&As[buf][kk][ty * 16 + 8]);
            float4 av3 = *reinterpret_cast<const float4*>(&As[buf][kk][ty * 16 + 12]);
            // B: 8 cols as 4x 64-bit pairs (2x LDS.128)
            const uint64_t* b64 = reinterpret_cast<const uint64_t*>(&Bs[buf][kk][tx * 8]);
            uint64_t bpair[4] = {b64[0], b64[1], b64[2], b64[3]};
            float av[16] = {av0.x, av0.y, av0.z, av0.w, av1.x, av1.y, av1.z, av1.w,
                            av2.x, av2.y, av2.z, av2.w, av3.x, av3.y, av3.z, av3.w};
#pragma unroll
            for (int i = 0; i < 16; i++) {
                uint64_t ad = dup2(av[i]);
#pragma unroll
                for (int jp = 0; jp < 4; jp++)
                    ffma2(acc2[i][jp], ad, bpair[jp]);
            }
        }
        if (t + 1 < NT) {
            int nb = buf ^ 1;
            As[nb][0][tid] = a00.x; As[nb][1][tid] = a00.y;
            As[nb][2][tid] = a00.z; As[nb][3][tid] = a00.w;
            As[nb][4][tid] = a01.x; As[nb][5][tid] = a01.y;
            As[nb][6][tid] = a01.z; As[nb][7][tid] = a01.w;
            As[nb][0][tid + 256] = a10.x; As[nb][1][tid + 256] = a10.y;
            As[nb][2][tid + 256] = a10.z; As[nb][3][tid + 256] = a10.w;
            As[nb][4][tid + 256] = a11.x; As[nb][5][tid + 256] = a11.y;
            As[nb][6][tid + 256] = a11.z; As[nb][7][tid + 256] = a11.w;
            Bs[nb][bkr][bcl] = b0.x; Bs[nb][bkr][bcl + 1] = b0.y;
            __syncthreads();
            buf = nb;
        }
    }

    int gc = col0 + tx * 8;
#pragma unroll
    for (int i = 0; i < 16; i++) {
        int r = row0 + ty * 16 + i;
        float o[8];
        unpack2(acc2[i][0], o[0], o[1]);
        unpack2(acc2[i][1], o[2], o[3]);
        unpack2(acc2[i][2], o[4], o[5]);
        unpack2(acc2[i][3], o[6], o[7]);
        if (BIAS) {
#pragma unroll
            for (int j = 0; j < 8; j++) o[j] = __fadd_rn(o[j], bias[gc + j]);
        }
        *reinterpret_cast<float4*>(C + (size_t)r * ldc + gc)     = make_float4(o[0], o[1], o[2], o[3]);
        *reinterpret_cast<float4*>(C + (size_t)r * ldc + gc + 4) = make_float4(o[4], o[5], o[6], o[7]);
    }
}

// ---------------- scores: warp-per-dot, lane-strided (stride 32) + shfl tree --------
// FROZEN — bit-matches the reference's score lowering (selection-critical).
__global__ void __launch_bounds__(256)
scores_topk_kernel(int* __restrict__ rowmap)
{
    int t = blockIdx.x;
    __shared__ float qs[CDIM];
    __shared__ float sc[PCACHE];
    int tid = threadIdx.x;
    for (int i = tid; i < CDIM; i += 256) qs[i] = d_P[(size_t)t * 960 + i];
    __syncthreads();

    int w = tid >> 5, lane = tid & 31;
#pragma unroll
    for (int r = 0; r < 4; r++) {
        int p = w * 4 + r;
        const float* krow = d_kpast + ((size_t)t * PCACHE + p) * CDIM;
        float acc = 0.f;
#pragma unroll
        for (int i = 0; i < CDIM / 32; i++)
            acc = __fmaf_rn(qs[lane + 32 * i], krow[lane + 32 * i], acc);
#pragma unroll
        for (int off = 16; off; off >>= 1)
            acc = __fadd_rn(acc, __shfl_down_sync(0xffffffffu, acc, off));
        if (lane == 0) sc[p] = acc;
    }
    __syncthreads();

    if (tid == 0) {
        unsigned used = 0;
#pragma unroll
        for (int j = 0; j < RSEL; j++) {
            float best = -3.402823466e38f; int bi = 0;
            for (int p = 0; p < PCACHE; p++) {
                if (!((used >> p) & 1u) && sc[p] > best) { best = sc[p]; bi = p; }
            }
            used |= (1u << bi);
            rowmap[t * RSEL + j] = t * PCACHE + bi;
        }
    }
}

// ---------------- attention: RoPE (mul/sub, no FMA), serial softmax, serial FMA ------
__global__ void __launch_bounds__(256)
attn_kernel(const int* __restrict__ rowmap)
{
    int t = blockIdx.x, tid = threadIdx.x;
    __shared__ float q[CDIM];
    __shared__ float kb[NKEY][CDIM];
    __shared__ float vb[NKEY][CDIM];
    __shared__ float sw[HEADS_][NKEY];
    __shared__ int rows[RSEL];

    if (tid < RSEL) rows[tid] = rowmap[t * RSEL + tid];
    for (int i = tid; i < CDIM; i += 256) q[i] = d_P[(size_t)t * 960 + i];
    __syncthreads();

    for (int i = tid; i < NKEY * CDIM; i += 256) {
        int j = i / CDIM, c = i - j * CDIM;
        kb[j][c] = (j < RSEL) ? d_kpast[(size_t)rows[j] * CDIM + c]
                              : d_P[(size_t)t * 960 + CDIM + c];       // k_now
        vb[j][c] = (j < RSEL) ? d_vsel[(size_t)(t * RSEL + j) * CDIM + c]
                              : d_P[(size_t)t * 960 + 2 * CDIM + c];   // v_now
    }
    __syncthreads();

    for (int pidx = tid; pidx < NKEY * (CDIM/2); pidx += 256) {
        int j = pidx / (CDIM/2), ip = pidx - j * (CDIM/2);
        float2 cs = d_rope[j * (CDIM/2) + ip];
        float e = kb[j][2*ip], o = kb[j][2*ip + 1];
        kb[j][2*ip]     = __fsub_rn(__fmul_rn(e, cs.x), __fmul_rn(o, cs.y));
        kb[j][2*ip + 1] = __fadd_rn(__fmul_rn(e, cs.y), __fmul_rn(o, cs.x));
    }
    __syncthreads();

    if (tid < HEADS_ * NKEY) {
        int h = tid / NKEY, j = tid - h * NKEY;
        float s = 0.f;
#pragma unroll
        for (int d = 0; d < DH; d++)
            s = __fmaf_rn(q[h * DH + d], kb[j][h * DH + d], s);
        sw[h][j] = __fmul_rn(s, 0.15811388300841897f);
    }
    __syncthreads();

    if (tid < HEADS_) {
        int h = tid;
        float mx = sw[h][0];
#pragma unroll
        for (int j = 1; j < NKEY; j++) mx = fmaxf(mx, sw[h][j]);
        float e[NKEY]; float sum = 0.f;
#pragma unroll
        for (int j = 0; j < NKEY; j++) {
            e[j] = expf(__fsub_rn(sw[h][j], mx));
            sum = __fadd_rn(sum, e[j]);
        }
#pragma unroll
        for (int j = 0; j < NKEY; j++) sw[h][j] = __fdiv_rn(e[j], sum);
    }
    __syncthreads();

    for (int c = tid; c < CDIM; c += 256) {
        int h = c / DH;
        float acc = 0.f;
#pragma unroll
        for (int j = 0; j < NKEY; j++)
            acc = __fmaf_rn(sw[h][j], vb[j][c], acc);
        d_ctx[(size_t)t * CDIM + c] = acc;
    }
}

// ---------------- launch ----------------
extern "C" void kernel_launch(void* const* d_in, const int* in_sizes, int n_in,
                              void* d_out, int out_size)
{
    const float* hidden = (const float*)d_in[0];
    const float* cached = (const float*)d_in[1];
    const float* Wq     = (const float*)d_in[2];
    const float* Wk     = (const float*)d_in[3];
    const float* Wv     = (const float*)d_in[4];
    const float* Wo     = (const float*)d_in[5];
    const float* bo     = (const float*)d_in[6];
    float* out = (float*)d_out;

    float *pW3, *pP, *pKpast, *pVsel, *pCtx;
    int* pRow;
    cudaGetSymbolAddress((void**)&pW3,    d_W3);
    cudaGetSymbolAddress((void**)&pP,     d_P);
    cudaGetSymbolAddress((void**)&pKpast, d_kpast);
    cudaGetSymbolAddress((void**)&pVsel,  d_vsel);
    cudaGetSymbolAddress((void**)&pCtx,   d_ctx);
    cudaGetSymbolAddress((void**)&pRow,   d_rowmap);

    rope_table_kernel<<<6, 256>>>();
    pack_W3_kernel<<<(CDIM * 3 * CDIM + 255) / 256, 256>>>(Wq, Wk, Wv);

    // [q_now | k_now | v_now] = hidden @ [Wq|Wk|Wv]   (16384 x 960)
    gemm_fast<false, false><<<dim3(960 / 64, NTOK / 512), 256>>>(
        hidden, pW3, pP, CDIM, CDIM, 960, 960, nullptr, nullptr);

    // k_past = cached @ Wk   (524288 x 320)
    gemm_fast<false, false><<<dim3(CDIM / 64, NTOK * PCACHE / 512), 256>>>(
        cached, Wk, pKpast, CDIM, CDIM, CDIM, CDIM, nullptr, nullptr);

    // scores (gemv2T-order, FROZEN) + top-8 -> rowmap
    scores_topk_kernel<<<NTOK, 256>>>(pRow);

    // v_sel = cached[rowmap] @ Wv   (131072 x 320)
    gemm_fast<true, false><<<dim3(CDIM / 64, NTOK * RSEL / 512), 256>>>(
        cached, Wv, pVsel, CDIM, CDIM, CDIM, CDIM, pRow, nullptr);

    // RoPE + attention + ctx
    attn_kernel<<<NTOK, 256>>>(pRow);

    // out = ctx @ Wo + bo
    gemm_fast<false, true><<<dim3(CDIM / 64, NTOK / 512), 256>>>(
        pCtx, Wo, out, CDIM, CDIM, CDIM, CDIM, nullptr, bo);
}

// round 14
// speedup vs baseline: 1.1119x; 1.0613x over previous
#include <cuda_runtime.h>
#include <cuda_bf16.h>
#include <math.h>
#include <stdint.h>

// Problem constants (from reference setup_inputs)
#define NTOK   16384      // B*D = 4*4096
#define CDIM   320
#define PCACHE 32
#define RSEL   8
#define HEADS_ 8
#define DH     40
#define NKEY   9          // RSEL + 1

// ---------------- device scratch (static, no allocs) ----------------
__device__ float  d_W3[CDIM * 3 * CDIM];                 // [Wq | Wk | Wv] (320 x 960)
__device__ float  d_P [NTOK * 3 * CDIM];                 // [q_now | k_now | v_now] (16384 x 960)
__device__ float  d_kpast[(size_t)NTOK * PCACHE * CDIM]; // full k_past (524288 x 320)
__device__ int    d_rowmap[NTOK * RSEL];                 // absolute cached-row index (t*32 + sel)
__device__ float  d_vsel[NTOK * RSEL * CDIM];            // selected v_past rows (131072 x 320)
__device__ float  d_ctx [NTOK * CDIM];                   // context before Wo
__device__ float2 d_rope[NKEY * (CDIM/2)];               // cos/sin per (pos, freq)

// ---------------- rope tables, fp32 libdevice semantics matching XLA ----------------
__global__ void rope_table_kernel()
{
    int idx = blockIdx.x * blockDim.x + threadIdx.x;
    if (idx >= NKEY * (CDIM/2)) return;
    int pos = idx / (CDIM/2);
    int ip  = idx - pos * (CDIM/2);
    float x   = __fdiv_rn((float)(2 * ip), (float)CDIM);
    float pw  = powf(10000.0f, x);
    float inv = __fdiv_rn(1.0f, pw);
    float ang = __fmul_rn((float)pos, inv);
    d_rope[idx] = make_float2(cosf(ang), sinf(ang));
}

// ---------------- prep: W3 = [Wq | Wk | Wv] (320 x 960) ----------------
__global__ void pack_W3_kernel(const float* __restrict__ Wq, const float* __restrict__ Wk,
                               const float* __restrict__ Wv)
{
    int idx = blockIdx.x * 256 + threadIdx.x;
    if (idx >= CDIM * 3 * CDIM) return;
    int a = idx / (3 * CDIM), j = idx - a * (3 * CDIM);
    float v;
    if (j < CDIM)            v = Wq[a * CDIM + j];
    else if (j < 2 * CDIM)   v = Wk[a * CDIM + j - CDIM];
    else                     v = Wv[a * CDIM + j - 2 * CDIM];
    d_W3[idx] = v;
}

// ---------------- packed-f32x2 helpers ----------------
// Each 32-bit lane of fma.rn.f32x2 rounds RN exactly like scalar __fmaf_rn: pairing two
// OUTPUT COLUMNS per 64-bit accumulator keeps every per-element chain bit-identical
// (single fp32 accumulator per output, FMA, k strictly ascending).
__device__ __forceinline__ uint64_t dup2(float v)
{
    uint64_t r;
    asm("mov.b64 %0, {%1, %1};" : "=l"(r) : "f"(v));
    return r;
}
__device__ __forceinline__ void ffma2(uint64_t& acc, uint64_t a, uint64_t b)
{
    asm("fma.rn.f32x2 %0, %1, %2, %0;" : "+l"(acc) : "l"(a), "l"(b));
}
__device__ __forceinline__ void unpack2(uint64_t v, float& lo, float& hi)
{
    asm("mov.b64 {%0, %1}, %2;" : "=f"(lo), "=f"(hi) : "l"(v));
}

// ---------------- fast fp32 GEMM (FFMA2): C = A(MxK) @ B(KxN) (+bias) ---------------
// BM=256, BN=64, BK=8, 256 threads, 8x8 per thread, double-buffered smem.
// Inner loops ordered jp-outer/i-inner so 8 consecutive FFMA2 share the SAME B operand
// (operand-collector .reuse -> dodge the 3-even/3-odd RF-bank cap).
// Per output element: ONE fp32 accumulator, FMA, k strictly ascending (bit-frozen).
// Requirements: M % 256 == 0, N % 64 == 0, K % 8 == 0.
template <bool GATHER, bool BIAS>
__global__ void __launch_bounds__(256, 2)
gemm_fast(const float* __restrict__ A, const float* __restrict__ B, float* __restrict__ C,
          int Kdim, int lda, int ldb, int ldc,
          const int* __restrict__ rowmap, const float* __restrict__ bias)
{
    const int BM = 256, BN = 64, BK = 8;
    __shared__ __align__(16) float As[2][BK][BM];
    __shared__ __align__(16) float Bs[2][BK][BN];

    int tid  = threadIdx.x;
    int row0 = blockIdx.x * BM;
    int col0 = blockIdx.y * BN;

    // A loads: 2 float4 per thread: rows ar0 and ar0+128, k-cols kc..kc+3
    int ar0 = tid >> 1;              // 0..127
    int kc  = (tid & 1) * 4;         // 0 or 4
    int g0 = row0 + ar0, g1 = row0 + ar0 + 128;
    if (GATHER) { g0 = rowmap[g0]; g1 = rowmap[g1]; }
    const float* ap0 = A + (size_t)g0 * lda + kc;
    const float* ap1 = A + (size_t)g1 * lda + kc;

    // B loads: 1 float2 per thread: k-row bkr, cols bcl..bcl+1
    int bkr = tid >> 5;              // 0..7
    int bcl = (tid & 31) * 2;        // 0..62
    const float* bp = B + (size_t)bkr * ldb + col0 + bcl;

    int tx = tid & 7, ty = tid >> 3; // tx: col octet 0..7, ty: row octet 0..31
    uint64_t acc2[8][4];             // [row i][col pair jp]
#pragma unroll
    for (int i = 0; i < 8; i++)
#pragma unroll
        for (int jp = 0; jp < 4; jp++) acc2[i][jp] = 0ull;

    int NT = Kdim / BK;

    // prefetch tile 0
    float4 a0 = *reinterpret_cast<const float4*>(ap0);
    float4 a1 = *reinterpret_cast<const float4*>(ap1);
    float2 b0 = *reinterpret_cast<const float2*>(bp);
    As[0][kc + 0][ar0] = a0.x; As[0][kc + 1][ar0] = a0.y;
    As[0][kc + 2][ar0] = a0.z; As[0][kc + 3][ar0] = a0.w;
    As[0][kc + 0][ar0 + 128] = a1.x; As[0][kc + 1][ar0 + 128] = a1.y;
    As[0][kc + 2][ar0 + 128] = a1.z; As[0][kc + 3][ar0 + 128] = a1.w;
    Bs[0][bkr][bcl] = b0.x; Bs[0][bkr][bcl + 1] = b0.y;
    __syncthreads();

    int buf = 0;
    for (int t = 0; t < NT; t++) {
        if (t + 1 < NT) {
            a0 = *reinterpret_cast<const float4*>(ap0 + (t + 1) * BK);
            a1 = *reinterpret_cast<const float4*>(ap1 + (t + 1) * BK);
            b0 = *reinterpret_cast<const float2*>(bp + (size_t)(t + 1) * BK * ldb);
        }
#pragma unroll
        for (int kk = 0; kk < BK; kk++) {   // ascending k: k = t*8 + kk
            float4 av0 = *reinterpret_cast<const float4*>(&As[buf][kk][ty * 8]);
            float4 av1 = *reinterpret_cast<const float4*>(&As[buf][kk][ty * 8 + 4]);
            const uint64_t* b64 = reinterpret_cast<const uint64_t*>(&Bs[buf][kk][tx * 8]);
            float av[8] = {av0.x, av0.y, av0.z, av0.w, av1.x, av1.y, av1.z, av1.w};
            uint64_t ad[8];
#pragma unroll
            for (int i = 0; i < 8; i++) ad[i] = dup2(av[i]);
            // jp-outer / i-inner: consecutive FFMA2 share the same b operand (.reuse)
#pragma unroll
            for (int jp = 0; jp < 4; jp++) {
                uint64_t bp2 = b64[jp];
#pragma unroll
                for (int i = 0; i < 8; i++)
                    ffma2(acc2[i][jp], ad[i], bp2);
            }
        }
        if (t + 1 < NT) {
            int nb = buf ^ 1;
            As[nb][kc + 0][ar0] = a0.x; As[nb][kc + 1][ar0] = a0.y;
            As[nb][kc + 2][ar0] = a0.z; As[nb][kc + 3][ar0] = a0.w;
            As[nb][kc + 0][ar0 + 128] = a1.x; As[nb][kc + 1][ar0 + 128] = a1.y;
            As[nb][kc + 2][ar0 + 128] = a1.z; As[nb][kc + 3][ar0 + 128] = a1.w;
            Bs[nb][bkr][bcl] = b0.x; Bs[nb][bkr][bcl + 1] = b0.y;
            __syncthreads();
            buf = nb;
        }
    }

    int gc = col0 + tx * 8;
#pragma unroll
    for (int i = 0; i < 8; i++) {
        int r = row0 + ty * 8 + i;
        float o[8];
        unpack2(acc2[i][0], o[0], o[1]);
        unpack2(acc2[i][1], o[2], o[3]);
        unpack2(acc2[i][2], o[4], o[5]);
        unpack2(acc2[i][3], o[6], o[7]);
        if (BIAS) {
#pragma unroll
            for (int j = 0; j < 8; j++) o[j] = __fadd_rn(o[j], bias[gc + j]);
        }
        *reinterpret_cast<float4*>(C + (size_t)r * ldc + gc)     = make_float4(o[0], o[1], o[2], o[3]);
        *reinterpret_cast<float4*>(C + (size_t)r * ldc + gc + 4) = make_float4(o[4], o[5], o[6], o[7]);
    }
}

// ---------------- scores: warp-per-dot, lane-strided (stride 32) + shfl tree --------
// FROZEN — bit-matches the reference's score lowering (selection-critical).
__global__ void __launch_bounds__(256)
scores_topk_kernel(int* __restrict__ rowmap)
{
    int t = blockIdx.x;
    __shared__ __align__(16) float qs[CDIM];
    __shared__ float sc[PCACHE];
    int tid = threadIdx.x;
    for (int i = tid; i < CDIM / 4; i += 256)
        reinterpret_cast<float4*>(qs)[i] =
            reinterpret_cast<const float4*>(d_P + (size_t)t * 960)[i];
    __syncthreads();

    int w = tid >> 5, lane = tid & 31;
#pragma unroll
    for (int r = 0; r < 4; r++) {
        int p = w * 4 + r;
        const float* krow = d_kpast + ((size_t)t * PCACHE + p) * CDIM;
        float acc = 0.f;
#pragma unroll
        for (int i = 0; i < CDIM / 32; i++)
            acc = __fmaf_rn(qs[lane + 32 * i], krow[lane + 32 * i], acc);
#pragma unroll
        for (int off = 16; off; off >>= 1)
            acc = __fadd_rn(acc, __shfl_down_sync(0xffffffffu, acc, off));
        if (lane == 0) sc[p] = acc;
    }
    __syncthreads();

    if (tid == 0) {
        unsigned used = 0;
#pragma unroll
        for (int j = 0; j < RSEL; j++) {
            float best = -3.402823466e38f; int bi = 0;
            for (int p = 0; p < PCACHE; p++) {
                if (!((used >> p) & 1u) && sc[p] > best) { best = sc[p]; bi = p; }
            }
            used |= (1u << bi);
            rowmap[t * RSEL + j] = t * PCACHE + bi;
        }
    }
}

// ---------------- attention: float4 staging, RoPE, serial softmax, serial FMA --------
__global__ void __launch_bounds__(256)
attn_kernel(const int* __restrict__ rowmap)
{
    int t = blockIdx.x, tid = threadIdx.x;
    __shared__ __align__(16) float q[CDIM];
    __shared__ __align__(16) float kb[NKEY][CDIM];
    __shared__ __align__(16) float vb[NKEY][CDIM];
    __shared__ float sw[HEADS_][NKEY];
    __shared__ int rows[RSEL];

    if (tid < RSEL) rows[tid] = rowmap[t * RSEL + tid];
    for (int i = tid; i < CDIM / 4; i += 256)
        reinterpret_cast<float4*>(q)[i] =
            reinterpret_cast<const float4*>(d_P + (size_t)t * 960)[i];
    __syncthreads();

    // stage kb/vb as float4 (all row bases 16B-aligned)
    for (int i = tid; i < NKEY * (CDIM / 4); i += 256) {
        int j = i / (CDIM / 4), c4 = i - j * (CDIM / 4);
        float4 kv, vv;
        if (j < RSEL) {
            kv = reinterpret_cast<const float4*>(d_kpast + (size_t)rows[j] * CDIM)[c4];
            vv = reinterpret_cast<const float4*>(d_vsel + (size_t)(t * RSEL + j) * CDIM)[c4];
        } else {
            kv = reinterpret_cast<const float4*>(d_P + (size_t)t * 960 + CDIM)[c4];
            vv = reinterpret_cast<const float4*>(d_P + (size_t)t * 960 + 2 * CDIM)[c4];
        }
        reinterpret_cast<float4*>(kb[j])[c4] = kv;
        reinterpret_cast<float4*>(vb[j])[c4] = vv;
    }
    __syncthreads();

    // RoPE on keys at position j (q at pos 0 is exact identity). mul/mul/sub|add, RN.
    for (int pidx = tid; pidx < NKEY * (CDIM/2); pidx += 256) {
        int j = pidx / (CDIM/2), ip = pidx - j * (CDIM/2);
        float2 cs = d_rope[j * (CDIM/2) + ip];
        float e = kb[j][2*ip], o = kb[j][2*ip + 1];
        kb[j][2*ip]     = __fsub_rn(__fmul_rn(e, cs.x), __fmul_rn(o, cs.y));
        kb[j][2*ip + 1] = __fadd_rn(__fmul_rn(e, cs.y), __fmul_rn(o, cs.x));
    }
    __syncthreads();

    if (tid < HEADS_ * NKEY) {
        int h = tid / NKEY, j = tid - h * NKEY;
        float s = 0.f;
#pragma unroll
        for (int d = 0; d < DH; d++)
            s = __fmaf_rn(q[h * DH + d], kb[j][h * DH + d], s);
        sw[h][j] = __fmul_rn(s, 0.15811388300841897f);
    }
    __syncthreads();

    if (tid < HEADS_) {
        int h = tid;
        float mx = sw[h][0];
#pragma unroll
        for (int j = 1; j < NKEY; j++) mx = fmaxf(mx, sw[h][j]);
        float e[NKEY]; float sum = 0.f;
#pragma unroll
        for (int j = 0; j < NKEY; j++) {
            e[j] = expf(__fsub_rn(sw[h][j], mx));
            sum = __fadd_rn(sum, e[j]);
        }
#pragma unroll
        for (int j = 0; j < NKEY; j++) sw[h][j] = __fdiv_rn(e[j], sum);
    }
    __syncthreads();

    for (int c = tid; c < CDIM; c += 256) {
        int h = c / DH;
        float acc = 0.f;
#pragma unroll
        for (int j = 0; j < NKEY; j++)
            acc = __fmaf_rn(sw[h][j], vb[j][c], acc);
        d_ctx[(size_t)t * CDIM + c] = acc;
    }
}

// ---------------- launch ----------------
extern "C" void kernel_launch(void* const* d_in, const int* in_sizes, int n_in,
                              void* d_out, int out_size)
{
    const float* hidden = (const float*)d_in[0];
    const float* cached = (const float*)d_in[1];
    const float* Wq     = (const float*)d_in[2];
    const float* Wk     = (const float*)d_in[3];
    const float* Wv     = (const float*)d_in[4];
    const float* Wo     = (const float*)d_in[5];
    const float* bo     = (const float*)d_in[6];
    float* out = (float*)d_out;

    float *pW3, *pP, *pKpast, *pVsel, *pCtx;
    int* pRow;
    cudaGetSymbolAddress((void**)&pW3,    d_W3);
    cudaGetSymbolAddress((void**)&pP,     d_P);
    cudaGetSymbolAddress((void**)&pKpast, d_kpast);
    cudaGetSymbolAddress((void**)&pVsel,  d_vsel);
    cudaGetSymbolAddress((void**)&pCtx,   d_ctx);
    cudaGetSymbolAddress((void**)&pRow,   d_rowmap);

    rope_table_kernel<<<6, 256>>>();
    pack_W3_kernel<<<(CDIM * 3 * CDIM + 255) / 256, 256>>>(Wq, Wk, Wv);

    // [q_now | k_now | v_now] = hidden @ [Wq|Wk|Wv]   (16384 x 960)
    gemm_fast<false, false><<<dim3(NTOK / 256, 960 / 64), 256>>>(
        hidden, pW3, pP, CDIM, CDIM, 960, 960, nullptr, nullptr);

    // k_past = cached @ Wk   (524288 x 320)
    gemm_fast<false, false><<<dim3(NTOK * PCACHE / 256, CDIM / 64), 256>>>(
        cached, Wk, pKpast, CDIM, CDIM, CDIM, CDIM, nullptr, nullptr);

    // scores (gemv2T-order, FROZEN) + top-8 -> rowmap
    scores_topk_kernel<<<NTOK, 256>>>(pRow);

    // v_sel = cached[rowmap] @ Wv   (131072 x 320)
    gemm_fast<true, false><<<dim3(NTOK * RSEL / 256, CDIM / 64), 256>>>(
        cached, Wv, pVsel, CDIM, CDIM, CDIM, CDIM, pRow, nullptr);

    // RoPE + attention + ctx
    attn_kernel<<<NTOK, 256>>>(pRow);

    // out = ctx @ Wo + bo
    gemm_fast<false, true><<<dim3(NTOK / 256, CDIM / 64), 256>>>(
        pCtx, Wo, out, CDIM, CDIM, CDIM, CDIM, nullptr, bo);
}